// round 6
// baseline (speedup 1.0000x reference)
#include <cuda_runtime.h>
#include <math.h>
#include <stdint.h>

#define TT     128
#define BB     64
#define IDIMq  256
#define CDIMq  512
#define RRq    4
#define NNq    128
#define WWq    64
#define IFACEq 471
#define EPSq   1e-6f
#define DELTAq 5e-6f
#define CATW   768
#define NBLK   128

// ---------------- static device scratch ----------------
__device__ float g_G   [(size_t)TT * BB * 4 * CDIMq];   // layer0 input pre-gates
__device__ float g_h0  [2 * BB * CDIMq];                // ping-pong
__device__ float g_h1  [2 * BB * CDIMq];                // ping-pong
__device__ float g_cat [(size_t)TT * BB * CATW];
__device__ float g_xi  [(size_t)TT * BB * IFACEq];
__device__ unsigned g_bar_cnt = 0;
__device__ unsigned g_bar_gen = 0;

__device__ __forceinline__ float sigm(float x)  { return 1.f / (1.f + expf(-x)); }
__device__ __forceinline__ float splus(float x) { return fmaxf(x, 0.f) + log1pf(expf(-fabsf(x))); }
__device__ __forceinline__ float warp_sum(float v) {
#pragma unroll
    for (int o = 16; o; o >>= 1) v += __shfl_xor_sync(0xffffffffu, v, o);
    return v;
}
__device__ __forceinline__ float warp_max(float v) {
#pragma unroll
    for (int o = 16; o; o >>= 1) v = fmaxf(v, __shfl_xor_sync(0xffffffffu, v, o));
    return v;
}

__device__ __forceinline__ void cp16(uint32_t dst, const void* src) {
    asm volatile("cp.async.cg.shared.global [%0], [%1], 16;" :: "r"(dst), "l"(src));
}
__device__ __forceinline__ void cp_commit_wait() {
    asm volatile("cp.async.commit_group;");
    asm volatile("cp.async.wait_group 0;");
}

// ---------------- two-phase grid barrier (all NBLK blocks co-resident) ----------------
__device__ __forceinline__ void grid_sync() {
    __syncthreads();
    if (threadIdx.x == 0) {
        __threadfence();
        unsigned gen = *(volatile unsigned*)&g_bar_gen;
        unsigned arr = atomicAdd(&g_bar_cnt, 1);
        if (arr == NBLK - 1) {
            atomicExch(&g_bar_cnt, 0);
            __threadfence();
            atomicExch(&g_bar_gen, gen + 1);
        } else {
            while (*(volatile unsigned*)&g_bar_gen == gen) { }
        }
        __threadfence();
    }
    __syncthreads();
}

__global__ void zero_init() {
    int i = blockIdx.x * blockDim.x + threadIdx.x;   // 128*512 = 65536
    g_h0[i] = 0.f;
    g_h1[i] = 0.f;
}

// ---------------- SGEMM: C[M,N] = A[M,K] @ B[N,K]^T + bias1 (+bias2) ----------------
__global__ void __launch_bounds__(256) sgemm_bt(
    const float* __restrict__ A, int lda,
    const float* __restrict__ B, int ldb,
    float* __restrict__ C, int ldc,
    const float* __restrict__ bias1, const float* __restrict__ bias2,
    int N, int K)
{
    __shared__ float As[8][128];
    __shared__ float Bs[8][128];
    const int m0 = blockIdx.y * 128, n0 = blockIdx.x * 128;
    const int tid = threadIdx.x;
    const int lrow = tid >> 1;
    const int lk = (tid & 1) * 4;
    const int tx = tid & 15, ty = tid >> 4;

    float acc[8][8];
#pragma unroll
    for (int i = 0; i < 8; i++)
#pragma unroll
        for (int j = 0; j < 8; j++) acc[i][j] = 0.f;

    for (int k0 = 0; k0 < K; k0 += 8) {
        float4 av = *(const float4*)(A + (size_t)(m0 + lrow) * lda + k0 + lk);
        As[lk + 0][lrow] = av.x; As[lk + 1][lrow] = av.y;
        As[lk + 2][lrow] = av.z; As[lk + 3][lrow] = av.w;
        int nr = n0 + lrow;
        float4 bv = make_float4(0.f, 0.f, 0.f, 0.f);
        if (nr < N) bv = *(const float4*)(B + (size_t)nr * ldb + k0 + lk);
        Bs[lk + 0][lrow] = bv.x; Bs[lk + 1][lrow] = bv.y;
        Bs[lk + 2][lrow] = bv.z; Bs[lk + 3][lrow] = bv.w;
        __syncthreads();
#pragma unroll
        for (int k = 0; k < 8; k++) {
            float4 a0 = *(float4*)&As[k][ty * 8 + 0];
            float4 a1 = *(float4*)&As[k][ty * 8 + 4];
            float4 b0 = *(float4*)&Bs[k][tx * 8 + 0];
            float4 b1 = *(float4*)&Bs[k][tx * 8 + 4];
            float ar[8] = {a0.x, a0.y, a0.z, a0.w, a1.x, a1.y, a1.z, a1.w};
            float br[8] = {b0.x, b0.y, b0.z, b0.w, b1.x, b1.y, b1.z, b1.w};
#pragma unroll
            for (int i = 0; i < 8; i++)
#pragma unroll
                for (int j = 0; j < 8; j++) acc[i][j] += ar[i] * br[j];
        }
        __syncthreads();
    }
#pragma unroll
    for (int i = 0; i < 8; i++) {
        int m = m0 + ty * 8 + i;
#pragma unroll
        for (int j = 0; j < 8; j++) {
            int n = n0 + tx * 8 + j;
            if (n < N) {
                float v = acc[i][j] + bias1[n];
                if (bias2) v += bias2[n];
                C[(size_t)m * ldc + n] = v;
            }
        }
    }
}

// ---------------- fused dual-layer pipelined LSTM ----------------
// 128 blocks x 512 threads. Block owns 4 layer0-features (16 gate rows, k=512,
// Whh0 in smem) + 4 layer1-features (16 gate rows, k=1024 = [Wih1 x h0 | Whh1 x h1];
// Wih1 in smem, Whh1 + h1 via L2). 129 pipeline steps: step p computes h0[p]
// (phase A, p<128) and h1[p-1] (phase B, p>=1). h0[p-1] staged once in smem,
// reused by both phases. c-states in registers. One grid barrier per step.
#define WP    516
#define WSKEW(r) ((r) * WP + ((r) >> 3) * 4)
#define HSKEW(b) ((b) * WP + ((b) >> 3) * 4)
#define W0_OFF  0
#define W1_OFF  8264
#define H0_OFF  16528
#define R_OFF   49584            // 16528 + 33056
#define FSM_FLOATS (49584 + 8192)   // 57776 floats = 231104 B

__global__ void __launch_bounds__(512, 1) lstm_fused(
    const float* __restrict__ Gpre_all,  // [TT][BB][2048]  layer0 ih + biases
    const float* __restrict__ Whh0,      // [2048][512]
    const float* __restrict__ Wih1,      // [2048][512]
    const float* __restrict__ Whh1,      // [2048][512]
    const float* __restrict__ bih1,
    const float* __restrict__ bhh1,
    float*       cat)                    // clip(h1) -> cols [0,512)
{
    extern __shared__ float sm[];
    float* W0sm = sm + W0_OFF;
    float* W1sm = sm + W1_OFF;
    float* Hsm  = sm + H0_OFF;
    float* Rsm  = sm + R_OFF;

    const int tid = threadIdx.x, bid = blockIdx.x;
    const int warp = tid >> 5, lane = tid & 31;
    const int tile = lane & 15, sub = lane >> 4;
    const int r0 = (tile >> 3) * 8, b0 = (tile & 7) * 8;
    const int kbA = warp * 32 + sub * 16;            // phase A: 16 k per thread
    const int wbase = WSKEW(r0);
    const int hbase = HSKEW(b0);
    const uint32_t hsm_u32 = (uint32_t)__cvta_generic_to_shared(Hsm);

    // stage Whh0 + Wih1 rows for this block's features (once)
    for (int idx = tid; idx < 16 * 128; idx += 512) {
        int r = idx >> 7, kq = idx & 127;
        int grow = (r >> 2) * 512 + bid * 4 + (r & 3);
        *(float4*)&W0sm[WSKEW(r) + kq * 4] = *(const float4*)&Whh0[(size_t)grow * 512 + kq * 4];
        *(float4*)&W1sm[WSKEW(r) + kq * 4] = *(const float4*)&Wih1[(size_t)grow * 512 + kq * 4];
    }

    // phase-B global operand pointers (constant rows)
    const float* w1rows[8];
    {
        int kh = (warp >= 8) ? ((warp - 8) * 64 + sub * 32) : 0;
#pragma unroll
        for (int i = 0; i < 8; i++) {
            int r = r0 + i;
            w1rows[i] = Whh1 + (size_t)((r >> 2) * 512 + bid * 4 + (r & 3)) * 512 + kh;
        }
    }

    const int jl = (tid & 255) >> 6;      // local feature 0..3
    const int bb = tid & 63;              // batch
    const int jf = bid * 4 + jl;          // global feature
    float c = 0.f;                        // c0 for tid<256, c1 for tid>=256
    float bias1g[4];
    if (tid >= 256) {
#pragma unroll
        for (int g = 0; g < 4; g++)
            bias1g[g] = bih1[g * 512 + jf] + bhh1[g * 512 + jf];
    }

    for (int p = 0; p <= TT; p++) {
        // ---- stage h0[p-1] into smem (zeroed buffer serves p=0) ----
        {
            const float4* hsrc = (const float4*)(g_h0 + (size_t)((p & 1) ^ 1) * BB * 512);
#pragma unroll
            for (int ii = 0; ii < 16; ii++) {
                int idx = tid + ii * 512;
                int b = idx >> 7, kq = idx & 127;
                cp16(hsm_u32 + (uint32_t)(HSKEW(b) + kq * 4) * 4u, hsrc + b * 128 + kq);
            }
            cp_commit_wait();
        }
        __syncthreads();

        // ================= PHASE A: layer0 step t0 = p =================
        if (p < TT) {
            float acc[8][8];
#pragma unroll
            for (int i = 0; i < 8; i++)
#pragma unroll
                for (int j = 0; j < 8; j++) acc[i][j] = 0.f;

            const float* wp0 = W0sm + wbase;
            const float* hp0 = Hsm + hbase;
#pragma unroll
            for (int j8 = 0; j8 < 4; j8++) {
                const int k = kbA + j8 * 4;
                float4 hv[8];
#pragma unroll
                for (int j = 0; j < 8; j++) hv[j] = *(const float4*)(hp0 + j * WP + k);
#pragma unroll
                for (int i = 0; i < 8; i++) {
                    float4 wv = *(const float4*)(wp0 + i * WP + k);
#pragma unroll
                    for (int j = 0; j < 8; j++)
                        acc[i][j] += wv.x * hv[j].x + wv.y * hv[j].y
                                   + wv.z * hv[j].z + wv.w * hv[j].w;
                }
            }
#pragma unroll
            for (int i = 0; i < 8; i++)
#pragma unroll
                for (int j = 0; j < 8; j++)
                    acc[i][j] += __shfl_xor_sync(0xffffffffu, acc[i][j], 16);

            if (warp >= 8 && lane < 16) {
#pragma unroll
                for (int i = 0; i < 8; i++) {
                    float* dst = &Rsm[(warp - 8) * 1024 + (r0 + i) * 64 + b0];
                    *(float4*)dst       = make_float4(acc[i][0], acc[i][1], acc[i][2], acc[i][3]);
                    *(float4*)(dst + 4) = make_float4(acc[i][4], acc[i][5], acc[i][6], acc[i][7]);
                }
            }
            __syncthreads();
            if (warp < 8 && lane < 16) {
#pragma unroll
                for (int i = 0; i < 8; i++) {
                    float* dst = &Rsm[warp * 1024 + (r0 + i) * 64 + b0];
                    float4 p0 = *(float4*)dst, p1 = *(float4*)(dst + 4);
                    p0.x += acc[i][0]; p0.y += acc[i][1]; p0.z += acc[i][2]; p0.w += acc[i][3];
                    p1.x += acc[i][4]; p1.y += acc[i][5]; p1.z += acc[i][6]; p1.w += acc[i][7];
                    *(float4*)dst = p0; *(float4*)(dst + 4) = p1;
                }
            }
            __syncthreads();

            if (tid < 256) {
                float g4[4];
#pragma unroll
                for (int g = 0; g < 4; g++) {
                    int r = g * 4 + jl;
                    float s = 0.f;
#pragma unroll
                    for (int q = 0; q < 8; q++) s += Rsm[q * 1024 + r * 64 + bb];
                    g4[g] = s;
                }
                const float* gp = Gpre_all + ((size_t)p * BB + bb) * 2048 + jf;
                float gi = g4[0] + __ldg(gp);
                float gf = g4[1] + __ldg(gp + 512);
                float gg = g4[2] + __ldg(gp + 1024);
                float go = g4[3] + __ldg(gp + 1536);
                c = sigm(gf) * c + sigm(gi) * tanhf(gg);
                float h = sigm(go) * tanhf(c);
                g_h0[(size_t)(p & 1) * BB * 512 + bb * 512 + jf] = h;
            }
        }
        __syncthreads();   // Rsm handoff A -> B (Hsm is read-only in both)

        // ============ PHASE B: layer1 step t1 = p-1 ============
        if (p >= 1) {
            float acc[8][8];
#pragma unroll
            for (int i = 0; i < 8; i++)
#pragma unroll
                for (int j = 0; j < 8; j++) acc[i][j] = 0.f;

            if (warp < 8) {
                // Wih1(smem) x h0[p-1](smem), k-chunk = warp*64 + sub*32
                const int kb = warp * 64 + sub * 32;
                const float* wp0 = W1sm + wbase;
                const float* hp0 = Hsm + hbase;
#pragma unroll
                for (int j8 = 0; j8 < 8; j8++) {
                    const int k = kb + j8 * 4;
                    float4 hv[8];
#pragma unroll
                    for (int j = 0; j < 8; j++) hv[j] = *(const float4*)(hp0 + j * WP + k);
#pragma unroll
                    for (int i = 0; i < 8; i++) {
                        float4 wv = *(const float4*)(wp0 + i * WP + k);
#pragma unroll
                        for (int j = 0; j < 8; j++)
                            acc[i][j] += wv.x * hv[j].x + wv.y * hv[j].y
                                       + wv.z * hv[j].z + wv.w * hv[j].w;
                    }
                }
            } else {
                // Whh1(L2) x h1[p-2](L2), k2-chunk = (warp-8)*64 + sub*32
                const float* h1p = g_h1 + (size_t)(p & 1) * BB * 512
                                 + b0 * 512 + ((warp - 8) * 64 + sub * 32);
#pragma unroll
                for (int j8 = 0; j8 < 8; j8++) {
                    const int k = j8 * 4;
                    float4 hv[8];
#pragma unroll
                    for (int j = 0; j < 8; j++) hv[j] = __ldcg((const float4*)(h1p + j * 512 + k));
#pragma unroll
                    for (int i = 0; i < 8; i++) {
                        float4 wv = __ldg((const float4*)(w1rows[i] + k));
#pragma unroll
                        for (int j = 0; j < 8; j++)
                            acc[i][j] += wv.x * hv[j].x + wv.y * hv[j].y
                                       + wv.z * hv[j].z + wv.w * hv[j].w;
                    }
                }
            }
#pragma unroll
            for (int i = 0; i < 8; i++)
#pragma unroll
                for (int j = 0; j < 8; j++)
                    acc[i][j] += __shfl_xor_sync(0xffffffffu, acc[i][j], 16);

            if (warp >= 8 && lane < 16) {
#pragma unroll
                for (int i = 0; i < 8; i++) {
                    float* dst = &Rsm[(warp - 8) * 1024 + (r0 + i) * 64 + b0];
                    *(float4*)dst       = make_float4(acc[i][0], acc[i][1], acc[i][2], acc[i][3]);
                    *(float4*)(dst + 4) = make_float4(acc[i][4], acc[i][5], acc[i][6], acc[i][7]);
                }
            }
            __syncthreads();
            if (warp < 8 && lane < 16) {
#pragma unroll
                for (int i = 0; i < 8; i++) {
                    float* dst = &Rsm[warp * 1024 + (r0 + i) * 64 + b0];
                    float4 p0 = *(float4*)dst, p1 = *(float4*)(dst + 4);
                    p0.x += acc[i][0]; p0.y += acc[i][1]; p0.z += acc[i][2]; p0.w += acc[i][3];
                    p1.x += acc[i][4]; p1.y += acc[i][5]; p1.z += acc[i][6]; p1.w += acc[i][7];
                    *(float4*)dst = p0; *(float4*)(dst + 4) = p1;
                }
            }
            __syncthreads();

            if (tid >= 256) {
                float g4[4];
#pragma unroll
                for (int g = 0; g < 4; g++) {
                    int r = g * 4 + jl;
                    float s = 0.f;
#pragma unroll
                    for (int q = 0; q < 8; q++) s += Rsm[q * 1024 + r * 64 + bb];
                    g4[g] = s + bias1g[g];
                }
                c = sigm(g4[1]) * c + sigm(g4[0]) * tanhf(g4[2]);
                float h = sigm(g4[3]) * tanhf(c);
                g_h1[(size_t)((p & 1) ^ 1) * BB * 512 + bb * 512 + jf] = h;
                cat[((size_t)(p - 1) * BB + bb) * CATW + jf] = fminf(fmaxf(h, -20.f), 20.f);
            }
        }

        if (p < TT) grid_sync();
    }
}

// ---------------- DNC memory module (unchanged) ----------------
struct MemSmem {
    float mem[NNq][WWq + 1];
    float link[NNq][NNq + 1];
    float prec[NNq], usage[NNq], ww[NNq];
    float rw[RRq][NNq], rw2[RRq][NNq], fwd[RRq][NNq], bwd[RRq][NNq], rc[RRq][NNq];
    float wc[NNq], u[NNq], su[NNq], pe[NNq], norms[NNq];
    int   rank[NNq];
    float rkeys[RRq][WWq];
    float wkey[WWq], wvec[WWq], erase[WWq];
    float rstr[RRq], fg[RRq], rknorm[RRq];
    float modes[RRq][3];
    float scal[8];
};
#define S_WSTR 0
#define S_AG   1
#define S_WG   2
#define S_KN   3
#define S_SWW  4

__global__ void __launch_bounds__(256) memory_kernel(
    const float* __restrict__ xi_all, float* __restrict__ cat)
{
    extern __shared__ __align__(16) char smraw[];
    MemSmem* s = (MemSmem*)smraw;
    const int b = blockIdx.x, tid = threadIdx.x;

    for (int i = tid; i < (int)(sizeof(MemSmem) / 4); i += 256) ((float*)smraw)[i] = 0.f;
    __syncthreads();

    for (int t = 0; t < TT; t++) {
        const float* xi = xi_all + ((size_t)t * BB + b) * IFACEq;

        { int r = tid >> 6, w = tid & 63; s->rkeys[r][w] = tanhf(xi[tid]); }
        if (tid < 64) {
            s->wkey[tid]  = tanhf(xi[260 + tid]);
            s->erase[tid] = sigm (xi[325 + tid]);
            s->wvec[tid]  = tanhf(xi[389 + tid]);
        } else if (tid < 68) s->rstr[tid - 64] = splus(xi[256 + tid - 64]);
        else if (tid < 72)   s->fg[tid - 68]   = sigm (xi[453 + tid - 68]);
        else if (tid == 72)  s->scal[S_WSTR]   = splus(xi[324]);
        else if (tid == 73)  s->scal[S_AG]     = sigm (xi[457]);
        else if (tid == 74)  s->scal[S_WG]     = sigm (xi[458]);
        else if (tid >= 80 && tid < 84) {
            int r = tid - 80;
            float x0 = xi[459 + 3*r], x1 = xi[460 + 3*r], x2 = xi[461 + 3*r];
            float m = fmaxf(x0, fmaxf(x1, x2));
            float e0 = expf(x0 - m), e1 = expf(x1 - m), e2 = expf(x2 - m);
            float inv = 1.f / (e0 + e1 + e2);
            s->modes[r][0] = e0*inv; s->modes[r][1] = e1*inv; s->modes[r][2] = e2*inv;
        }
        __syncthreads();

        if (tid < 128) {
            float us = s->usage[tid] + (1.f - s->usage[tid]) * s->ww[tid];
            float ret = 1.f;
#pragma unroll
            for (int r = 0; r < RRq; r++) ret *= (1.f - s->fg[r] * s->rw[r][tid]);
            s->usage[tid] = us * ret;
            float ss = 0.f;
#pragma unroll 8
            for (int w = 0; w < WWq; w++) { float v = s->mem[tid][w]; ss += v * v; }
            s->norms[tid] = sqrtf(ss);
        } else if (tid < 160) {
            int l = tid - 128;
            float pq = s->wkey[l]*s->wkey[l] + s->wkey[l+32]*s->wkey[l+32];
            pq = warp_sum(pq);
            if (l == 0) s->scal[S_KN] = sqrtf(pq);
        } else if (tid < 164) {
            int r = tid - 160; float ss = 0.f;
            for (int w = 0; w < WWq; w++) ss += s->rkeys[r][w]*s->rkeys[r][w];
            s->rknorm[r] = sqrtf(ss);
        }
        __syncthreads();

        if (tid < 128) {
            float d = 0.f;
#pragma unroll 8
            for (int w = 0; w < WWq; w++) d += s->wkey[w] * s->mem[tid][w];
            s->wc[tid] = d / ((s->norms[tid] + EPSq) * (s->scal[S_KN] + EPSq)) * s->scal[S_WSTR];
        }
        __syncthreads();
        if (tid < 32) {
            float v0 = s->wc[tid], v1 = s->wc[tid+32], v2 = s->wc[tid+64], v3 = s->wc[tid+96];
            float mx = warp_max(fmaxf(fmaxf(v0, v1), fmaxf(v2, v3)));
            v0 = expf(v0-mx); v1 = expf(v1-mx); v2 = expf(v2-mx); v3 = expf(v3-mx);
            float inv = 1.f / warp_sum(v0 + v1 + v2 + v3);
            s->wc[tid] = v0*inv; s->wc[tid+32] = v1*inv; s->wc[tid+64] = v2*inv; s->wc[tid+96] = v3*inv;
        }
        __syncthreads();

        if (tid < 128) s->u[tid] = DELTAq + (1.f - DELTAq) * s->usage[tid];
        __syncthreads();
        if (tid < 128) {
            float ui = s->u[tid]; int rk = 0;
            for (int j = 0; j < 128; j++) {
                float uj = s->u[j];
                rk += (uj < ui) || (uj == ui && j < tid);
            }
            s->rank[tid] = rk;
            s->su[rk] = ui;
        }
        __syncthreads();
        if (tid < 128) s->pe[tid] = s->su[tid];
        __syncthreads();
        for (int d = 1; d < 128; d <<= 1) {
            float v = 1.f;
            if (tid < 128 && tid >= d) v = s->pe[tid - d];
            __syncthreads();
            if (tid < 128 && tid >= d) s->pe[tid] *= v;
            __syncthreads();
        }
        if (tid < 128) {
            int rk = s->rank[tid];
            float excl = rk ? s->pe[rk - 1] : 1.f;
            float alloc = (1.f - s->u[tid]) * excl;
            float ag = s->scal[S_AG], wg = s->scal[S_WG];
            s->ww[tid] = wg * (ag * alloc + (1.f - ag) * s->wc[tid]);
        }
        __syncthreads();
        if (tid < 32) {
            float v = s->ww[tid] + s->ww[tid+32] + s->ww[tid+64] + s->ww[tid+96];
            v = warp_sum(v);
            if (tid == 0) s->scal[S_SWW] = v;
        }
        __syncthreads();

        {
            int w = tid & 63, ng = tid >> 6;
            for (int i = 0; i < 32; i++) {
                int n = ng * 32 + i;
                float wwn = s->ww[n];
                s->mem[n][w] = s->mem[n][w] * (1.f - wwn * s->erase[w]) + wwn * s->wvec[w];
            }
        }
        {
            int i = tid >> 1, j0 = (tid & 1) * 64;
            float wwi = s->ww[i];
            for (int jj = 0; jj < 64; jj++) {
                int j = j0 + jj;
                float l = (1.f - wwi - s->ww[j]) * s->link[i][j] + wwi * s->prec[j];
                s->link[i][j] = (i == j) ? 0.f : l;
            }
        }
        __syncthreads();
        if (tid < 128) {
            s->prec[tid] = (1.f - s->scal[S_SWW]) * s->prec[tid] + s->ww[tid];
            float ss = 0.f;
#pragma unroll 8
            for (int w = 0; w < WWq; w++) { float v = s->mem[tid][w]; ss += v * v; }
            s->norms[tid] = sqrtf(ss);
        }
        __syncthreads();

        for (int q = tid; q < 512; q += 256) {
            int r = q >> 7, n = q & 127;
            float d = 0.f;
#pragma unroll 8
            for (int w = 0; w < WWq; w++) d += s->rkeys[r][w] * s->mem[n][w];
            s->rc[r][n] = d / ((s->norms[n] + EPSq) * (s->rknorm[r] + EPSq)) * s->rstr[r];
        }
        __syncthreads();
        if (tid < 128) {
            int r = tid >> 5, l = tid & 31;
            float v0 = s->rc[r][l], v1 = s->rc[r][l+32], v2 = s->rc[r][l+64], v3 = s->rc[r][l+96];
            float mx = warp_max(fmaxf(fmaxf(v0, v1), fmaxf(v2, v3)));
            v0 = expf(v0-mx); v1 = expf(v1-mx); v2 = expf(v2-mx); v3 = expf(v3-mx);
            float inv = 1.f / warp_sum(v0 + v1 + v2 + v3);
            s->rc[r][l] = v0*inv; s->rc[r][l+32] = v1*inv; s->rc[r][l+64] = v2*inv; s->rc[r][l+96] = v3*inv;
        }
        __syncthreads();

        for (int q = tid; q < 512; q += 256) {
            int r = q >> 7, n = q & 127;
            float f = 0.f, bw = 0.f;
#pragma unroll 4
            for (int m = 0; m < 128; m++) {
                float rv = s->rw[r][m];
                f  += rv * s->link[n][m];
                bw += rv * s->link[m][n];
            }
            s->fwd[r][n] = f; s->bwd[r][n] = bw;
        }
        __syncthreads();
        for (int q = tid; q < 512; q += 256) {
            int r = q >> 7, n = q & 127;
            s->rw2[r][n] = s->modes[r][0]*s->bwd[r][n] + s->modes[r][1]*s->rc[r][n] + s->modes[r][2]*s->fwd[r][n];
        }
        __syncthreads();
        for (int q = tid; q < 512; q += 256) { int r = q >> 7, n = q & 127; s->rw[r][n] = s->rw2[r][n]; }
        __syncthreads();

        {
            int r = tid >> 6, w = tid & 63;
            float acc = 0.f;
#pragma unroll 4
            for (int n = 0; n < 128; n++) acc += s->rw[r][n] * s->mem[n][w];
            cat[((size_t)t * BB + b) * CATW + 512 + tid] = acc;
        }
        __syncthreads();
    }
}

__global__ void gather_hid(float* __restrict__ out, const int* __restrict__ lens) {
    int b = blockIdx.x, i = threadIdx.x;
    int t = lens[b] - 1;
    out[(size_t)TT * BB * IDIMq + (size_t)b * IDIMq + i] = out[((size_t)t * BB + b) * IDIMq + i];
}

extern "C" void kernel_launch(void* const* d_in, const int* in_sizes, int n_in,
                              void* d_out, int out_size) {
    const float* embs = (const float*)d_in[0];
    const int*   lens = (const int*)  d_in[1];
    const float* Wih0 = (const float*)d_in[2];
    const float* Whh0 = (const float*)d_in[3];
    const float* bih0 = (const float*)d_in[4];
    const float* bhh0 = (const float*)d_in[5];
    const float* Wih1 = (const float*)d_in[6];
    const float* Whh1 = (const float*)d_in[7];
    const float* bih1 = (const float*)d_in[8];
    const float* bhh1 = (const float*)d_in[9];
    const float* Wxi  = (const float*)d_in[10];
    const float* bxi  = (const float*)d_in[11];
    const float* Wout = (const float*)d_in[12];
    const float* bout = (const float*)d_in[13];
    float* out = (float*)d_out;

    float *G, *cat, *xi;
    cudaGetSymbolAddress((void**)&G,   g_G);
    cudaGetSymbolAddress((void**)&cat, g_cat);
    cudaGetSymbolAddress((void**)&xi,  g_xi);

    cudaFuncSetAttribute(memory_kernel, cudaFuncAttributeMaxDynamicSharedMemorySize,
                         (int)sizeof(MemSmem));
    cudaFuncSetAttribute(lstm_fused, cudaFuncAttributeMaxDynamicSharedMemorySize,
                         FSM_FLOATS * 4);

    zero_init<<<128, 512>>>();

    // Gpre0 = embs @ Wih0[:, :256]^T + bih0 + bhh0   (zeros_read contributes nothing)
    sgemm_bt<<<dim3(16, 64), 256>>>(embs, IDIMq, Wih0, CDIMq, G, 2048, bih0, bhh0, 2048, IDIMq);

    // both LSTM layers, pipelined, one persistent kernel (sgemm2 folded in)
    lstm_fused<<<NBLK, 512, FSM_FLOATS * 4>>>(G, Whh0, Wih1, Whh1, bih1, bhh1, cat);

    // xi = clip(h1) @ Wxi^T + bxi
    sgemm_bt<<<dim3(4, 64), 256>>>(cat, CATW, Wxi, CDIMq, xi, IFACEq, bxi, nullptr, IFACEq, CDIMq);

    memory_kernel<<<64, 256, sizeof(MemSmem)>>>(xi, cat);

    // y = cat @ Wout^T + bout
    sgemm_bt<<<dim3(2, 64), 256>>>(cat, CATW, Wout, CATW, out, IDIMq, bout, nullptr, IDIMq, CATW);

    gather_hid<<<64, 256>>>(out, lens);
}

// round 7
// speedup vs baseline: 1.2089x; 1.2089x over previous
#include <cuda_runtime.h>
#include <math.h>
#include <stdint.h>

#define TT     128
#define BB     64
#define IDIMq  256
#define CDIMq  512
#define RRq    4
#define NNq    128
#define WWq    64
#define IFACEq 471
#define EPSq   1e-6f
#define DELTAq 5e-6f
#define CATW   768
#define NBLK   128

// ---------------- static device scratch ----------------
__device__ float g_G   [(size_t)TT * 2048 * BB];   // TRANSPOSED pre-gates [t][gate][bb]
__device__ float g_h0  [(size_t)TT * BB * CDIMq];
__device__ float g_h1  [(size_t)TT * BB * CDIMq];
__device__ float g_cat [(size_t)TT * BB * CATW];
__device__ float g_xi  [(size_t)TT * BB * IFACEq];
__device__ __align__(128) unsigned g_bar_cnt = 0;
__device__ __align__(128) unsigned g_bar_gen = 0;

__device__ __forceinline__ float sigm(float x)  { return 1.f / (1.f + expf(-x)); }
__device__ __forceinline__ float splus(float x) { return fmaxf(x, 0.f) + log1pf(expf(-fabsf(x))); }
__device__ __forceinline__ float warp_sum(float v) {
#pragma unroll
    for (int o = 16; o; o >>= 1) v += __shfl_xor_sync(0xffffffffu, v, o);
    return v;
}
__device__ __forceinline__ float warp_max(float v) {
#pragma unroll
    for (int o = 16; o; o >>= 1) v = fmaxf(v, __shfl_xor_sync(0xffffffffu, v, o));
    return v;
}

__device__ __forceinline__ void cp16(uint32_t dst, const void* src) {
    asm volatile("cp.async.cg.shared.global [%0], [%1], 16;" :: "r"(dst), "l"(src));
}
__device__ __forceinline__ void cp_commit() {
    asm volatile("cp.async.commit_group;");
}
__device__ __forceinline__ void cp_wait1() {
    asm volatile("cp.async.wait_group 1;");
}

// packed fp32x2 FMA: d.lo += a.lo*b.lo; d.hi += a.hi*b.hi
__device__ __forceinline__ void fma2(unsigned long long& d,
                                     unsigned long long a, unsigned long long b) {
    asm("fma.rn.f32x2 %0, %1, %2, %0;" : "+l"(d) : "l"(a), "l"(b));
}
__device__ __forceinline__ float unpack_sum(unsigned long long v) {
    float lo, hi;
    asm("mov.b64 {%0, %1}, %2;" : "=f"(lo), "=f"(hi) : "l"(v));
    return lo + hi;
}

// ---------------- two-phase grid barrier (all NBLK blocks co-resident) ----------------
__device__ __forceinline__ void grid_sync() {
    __syncthreads();
    if (threadIdx.x == 0) {
        __threadfence();
        unsigned gen = *(volatile unsigned*)&g_bar_gen;
        unsigned arr = atomicAdd(&g_bar_cnt, 1);
        if (arr == NBLK - 1) {
            atomicExch(&g_bar_cnt, 0);
            __threadfence();
            atomicExch(&g_bar_gen, gen + 1);
        } else {
            while (*(volatile unsigned*)&g_bar_gen == gen) { }
        }
        __threadfence();
    }
    __syncthreads();
}

// ---------------- SGEMM: C[M,N] = A[M,K] @ B[N,K]^T + bias1 (+bias2) ----------------
__global__ void __launch_bounds__(256) sgemm_bt(
    const float* __restrict__ A, int lda,
    const float* __restrict__ B, int ldb,
    float* __restrict__ C, int ldc,
    const float* __restrict__ bias1, const float* __restrict__ bias2,
    int N, int K)
{
    __shared__ float As[8][128];
    __shared__ float Bs[8][128];
    const int m0 = blockIdx.y * 128, n0 = blockIdx.x * 128;
    const int tid = threadIdx.x;
    const int lrow = tid >> 1;
    const int lk = (tid & 1) * 4;
    const int tx = tid & 15, ty = tid >> 4;

    float acc[8][8];
#pragma unroll
    for (int i = 0; i < 8; i++)
#pragma unroll
        for (int j = 0; j < 8; j++) acc[i][j] = 0.f;

    for (int k0 = 0; k0 < K; k0 += 8) {
        float4 av = *(const float4*)(A + (size_t)(m0 + lrow) * lda + k0 + lk);
        As[lk + 0][lrow] = av.x; As[lk + 1][lrow] = av.y;
        As[lk + 2][lrow] = av.z; As[lk + 3][lrow] = av.w;
        int nr = n0 + lrow;
        float4 bv = make_float4(0.f, 0.f, 0.f, 0.f);
        if (nr < N) bv = *(const float4*)(B + (size_t)nr * ldb + k0 + lk);
        Bs[lk + 0][lrow] = bv.x; Bs[lk + 1][lrow] = bv.y;
        Bs[lk + 2][lrow] = bv.z; Bs[lk + 3][lrow] = bv.w;
        __syncthreads();
#pragma unroll
        for (int k = 0; k < 8; k++) {
            float4 a0 = *(float4*)&As[k][ty * 8 + 0];
            float4 a1 = *(float4*)&As[k][ty * 8 + 4];
            float4 b0 = *(float4*)&Bs[k][tx * 8 + 0];
            float4 b1 = *(float4*)&Bs[k][tx * 8 + 4];
            float ar[8] = {a0.x, a0.y, a0.z, a0.w, a1.x, a1.y, a1.z, a1.w};
            float br[8] = {b0.x, b0.y, b0.z, b0.w, b1.x, b1.y, b1.z, b1.w};
#pragma unroll
            for (int i = 0; i < 8; i++)
#pragma unroll
                for (int j = 0; j < 8; j++) acc[i][j] += ar[i] * br[j];
        }
        __syncthreads();
    }
#pragma unroll
    for (int i = 0; i < 8; i++) {
        int m = m0 + ty * 8 + i;
#pragma unroll
        for (int j = 0; j < 8; j++) {
            int n = n0 + tx * 8 + j;
            if (n < N) {
                float v = acc[i][j] + bias1[n];
                if (bias2) v += bias2[n];
                C[(size_t)m * ldc + n] = v;
            }
        }
    }
}

// ---- variant writing transposed pre-gates: C[t][n][bb], t = m>>6, bb = m&63 ----
__global__ void __launch_bounds__(256) sgemm_bt_tg(
    const float* __restrict__ A, int lda,
    const float* __restrict__ B, int ldb,
    float* __restrict__ C,
    const float* __restrict__ bias1, const float* __restrict__ bias2,
    int N, int K)
{
    __shared__ float As[8][128];
    __shared__ float Bs[8][128];
    const int m0 = blockIdx.y * 128, n0 = blockIdx.x * 128;
    const int tid = threadIdx.x;
    const int lrow = tid >> 1;
    const int lk = (tid & 1) * 4;
    const int tx = tid & 15, ty = tid >> 4;

    float acc[8][8];
#pragma unroll
    for (int i = 0; i < 8; i++)
#pragma unroll
        for (int j = 0; j < 8; j++) acc[i][j] = 0.f;

    for (int k0 = 0; k0 < K; k0 += 8) {
        float4 av = *(const float4*)(A + (size_t)(m0 + lrow) * lda + k0 + lk);
        As[lk + 0][lrow] = av.x; As[lk + 1][lrow] = av.y;
        As[lk + 2][lrow] = av.z; As[lk + 3][lrow] = av.w;
        float4 bv = *(const float4*)(B + (size_t)(n0 + lrow) * ldb + k0 + lk);
        Bs[lk + 0][lrow] = bv.x; Bs[lk + 1][lrow] = bv.y;
        Bs[lk + 2][lrow] = bv.z; Bs[lk + 3][lrow] = bv.w;
        __syncthreads();
#pragma unroll
        for (int k = 0; k < 8; k++) {
            float4 a0 = *(float4*)&As[k][ty * 8 + 0];
            float4 a1 = *(float4*)&As[k][ty * 8 + 4];
            float4 b0 = *(float4*)&Bs[k][tx * 8 + 0];
            float4 b1 = *(float4*)&Bs[k][tx * 8 + 4];
            float ar[8] = {a0.x, a0.y, a0.z, a0.w, a1.x, a1.y, a1.z, a1.w};
            float br[8] = {b0.x, b0.y, b0.z, b0.w, b1.x, b1.y, b1.z, b1.w};
#pragma unroll
            for (int i = 0; i < 8; i++)
#pragma unroll
                for (int j = 0; j < 8; j++) acc[i][j] += ar[i] * br[j];
        }
        __syncthreads();
    }
#pragma unroll
    for (int i = 0; i < 8; i++) {
        int m = m0 + ty * 8 + i;
        int t = m >> 6, bbm = m & 63;
#pragma unroll
        for (int j = 0; j < 8; j++) {
            int n = n0 + tx * 8 + j;
            float v = acc[i][j] + bias1[n] + bias2[n];
            C[(size_t)t * 131072 + (size_t)n * 64 + bbm] = v;
        }
    }
}

// ---------------- persistent LSTM layer (R4 base + G-prefetch + f32x2 + gathered h store) ----------------
// 128 blocks x 256 threads; block owns 4 h-features (16 gate-rows of Whh in smem).
#define WPITCH 520
#define W_OFF  0
#define H_OFF  8320
#define R_OFF  41680              // 8320 + 33360
#define G_OFF  49872              // + 8192
#define HB_OFF 51920              // + 2048
#define SM_FLOATS 52176           // + 256   => 208704 bytes

__global__ void __launch_bounds__(256, 1) lstm_persist(
    const float* __restrict__ Gt,        // [TT][2048][64] transposed pre-gates
    const float* __restrict__ Whh,       // [2048][512]
    float*       hhist,                  // [TT][BB][512]
    float*       clipout)                // null or g_cat base
{
    extern __shared__ float sm[];
    float* Wsm  = sm + W_OFF;
    float* Hsm  = sm + H_OFF;
    float* Rsm  = sm + R_OFF;
    float* Gsm  = sm + G_OFF;
    float* Hbuf = sm + HB_OFF;

    const int tid = threadIdx.x, bid = blockIdx.x;
    const int warp = tid >> 5, lane = tid & 31;
    const int tile = lane & 15, sub = lane >> 4;
    const int r0 = (tile >> 3) * 8, b0 = (tile & 7) * 8;
    const int kb = warp * 64 + sub * 32;
    const int wbase = r0 * WPITCH + (r0 >> 3) * 8;
    const int hbase = b0 * WPITCH + (b0 >> 3) * 12;
    const uint32_t sm_u32  = (uint32_t)__cvta_generic_to_shared(sm);
    const uint32_t hsm_u32 = sm_u32 + H_OFF * 4;
    const uint32_t gsm_u32 = sm_u32 + G_OFF * 4;

    // stage this block's 16 gate-rows of Whh once
    for (int idx = tid; idx < 16 * 128; idx += 256) {
        int r = idx >> 7, kq = idx & 127;
        int grow = (r >> 2) * 512 + bid * 4 + (r & 3);
        *(float4*)&Wsm[r * WPITCH + (r >> 3) * 8 + kq * 4] =
            *(const float4*)&Whh[(size_t)grow * 512 + kq * 4];
    }

    // prefetch G slice for t=0 (1 cp16 per thread: 4KB = 4 segments of 1KB)
    {
        const float* src = Gt + (size_t)(tid >> 6) * 32768 + bid * 256 + (tid & 63) * 4;
        cp16(gsm_u32 + tid * 16, src);
        cp_commit();
    }

    const int jl = tid >> 6;        // local feature 0..3
    const int bb = tid & 63;        // batch
    const int jf = bid * 4 + jl;    // global feature
    float c = 0.f;

    for (int t = 0; t < TT; t++) {
        // ---- stage h(t-1) into skewed smem ----
        if (t == 0) {
            for (int idx = tid; idx < 64 * 128; idx += 256) {
                int b = idx >> 7, kq = idx & 127;
                *(float4*)&Hsm[b * WPITCH + (b >> 3) * 12 + kq * 4] = make_float4(0.f, 0.f, 0.f, 0.f);
            }
        } else {
            const float4* hsrc = (const float4*)(hhist + (size_t)(t - 1) * BB * 512);
#pragma unroll
            for (int ii = 0; ii < 32; ii++) {
                int idx = tid + ii * 256;
                int b = idx >> 7, kq = idx & 127;
                cp16(hsm_u32 + (uint32_t)(b * WPITCH + (b >> 3) * 12 + kq * 4) * 4u,
                     hsrc + b * 128 + kq);
            }
        }
        cp_commit();                               // group B_t
        if (t + 1 < TT) {                          // prefetch G slice for t+1
            const float* src = Gt + (size_t)(t + 1) * 131072
                             + (size_t)(tid >> 6) * 32768 + bid * 256 + (tid & 63) * 4;
            cp16(gsm_u32 + (uint32_t)(((t + 1) & 1) * 4096) + tid * 16, src);
        }
        cp_commit();                               // group C_t
        cp_wait1();                                // B_t + C_{t-1} done, C_t in flight
        __syncthreads();

        // ---- 8x8 register-tile matvec, f32x2 packed, 32-k chunk per thread ----
        unsigned long long acc2[8][8];
#pragma unroll
        for (int i = 0; i < 8; i++)
#pragma unroll
            for (int j = 0; j < 8; j++) acc2[i][j] = 0ull;

        const float* wp0 = Wsm + wbase;
        const float* hp0 = Hsm + hbase;
#pragma unroll
        for (int j8 = 0; j8 < 8; j8++) {
            const int k = kb + j8 * 4;
            ulonglong2 hv[8];
#pragma unroll
            for (int j = 0; j < 8; j++) hv[j] = *(const ulonglong2*)(hp0 + j * WPITCH + k);
#pragma unroll
            for (int i = 0; i < 8; i++) {
                ulonglong2 wv = *(const ulonglong2*)(wp0 + i * WPITCH + k);
#pragma unroll
                for (int j = 0; j < 8; j++) {
                    fma2(acc2[i][j], wv.x, hv[j].x);
                    fma2(acc2[i][j], wv.y, hv[j].y);
                }
            }
        }

        // collapse pairs, combine sub halves in-warp
        float acc[8][8];
#pragma unroll
        for (int i = 0; i < 8; i++)
#pragma unroll
            for (int j = 0; j < 8; j++) {
                float v = unpack_sum(acc2[i][j]);
                v += __shfl_xor_sync(0xffffffffu, v, 16);
                acc[i][j] = v;
            }

        if (lane < 16) {
#pragma unroll
            for (int i = 0; i < 8; i++) {
                float* dst = &Rsm[warp * 1024 + (r0 + i) * 64 + b0];
                *(float4*)dst       = make_float4(acc[i][0], acc[i][1], acc[i][2], acc[i][3]);
                *(float4*)(dst + 4) = make_float4(acc[i][4], acc[i][5], acc[i][6], acc[i][7]);
            }
        }
        __syncthreads();

        // ---- gate math: sum 8 warp-partials + prefetched Gpre (smem), update c,h ----
        {
            const float* gs = Gsm + (t & 1) * 1024;
            float g4[4];
#pragma unroll
            for (int g = 0; g < 4; g++) {
                int r = g * 4 + jl;
                float s = 0.f;
#pragma unroll
                for (int p = 0; p < 8; p++) s += Rsm[p * 1024 + r * 64 + bb];
                g4[g] = s + gs[g * 256 + tid];
            }
            c = sigm(g4[1]) * c + sigm(g4[0]) * tanhf(g4[2]);
            float h = sigm(g4[3]) * tanhf(c);
            Hbuf[bb * 4 + jl] = h;
        }
        __syncthreads();

        // ---- gathered coalesced store: 64 threads emit STG.128 ----
        if (tid < 64) {
            float4 v = *(float4*)&Hbuf[tid * 4];
            *(float4*)&hhist[(size_t)t * BB * 512 + (size_t)tid * 512 + bid * 4] = v;
            if (clipout) {
                float4 cv;
                cv.x = fminf(fmaxf(v.x, -20.f), 20.f);
                cv.y = fminf(fmaxf(v.y, -20.f), 20.f);
                cv.z = fminf(fmaxf(v.z, -20.f), 20.f);
                cv.w = fminf(fmaxf(v.w, -20.f), 20.f);
                *(float4*)&clipout[((size_t)t * BB + tid) * CATW + bid * 4] = cv;
            }
        }

        if (t + 1 < TT) grid_sync();
    }
}

// ---------------- DNC memory module (unchanged) ----------------
struct MemSmem {
    float mem[NNq][WWq + 1];
    float link[NNq][NNq + 1];
    float prec[NNq], usage[NNq], ww[NNq];
    float rw[RRq][NNq], rw2[RRq][NNq], fwd[RRq][NNq], bwd[RRq][NNq], rc[RRq][NNq];
    float wc[NNq], u[NNq], su[NNq], pe[NNq], norms[NNq];
    int   rank[NNq];
    float rkeys[RRq][WWq];
    float wkey[WWq], wvec[WWq], erase[WWq];
    float rstr[RRq], fg[RRq], rknorm[RRq];
    float modes[RRq][3];
    float scal[8];
};
#define S_WSTR 0
#define S_AG   1
#define S_WG   2
#define S_KN   3
#define S_SWW  4

__global__ void __launch_bounds__(256) memory_kernel(
    const float* __restrict__ xi_all, float* __restrict__ cat)
{
    extern __shared__ __align__(16) char smraw[];
    MemSmem* s = (MemSmem*)smraw;
    const int b = blockIdx.x, tid = threadIdx.x;

    for (int i = tid; i < (int)(sizeof(MemSmem) / 4); i += 256) ((float*)smraw)[i] = 0.f;
    __syncthreads();

    for (int t = 0; t < TT; t++) {
        const float* xi = xi_all + ((size_t)t * BB + b) * IFACEq;

        { int r = tid >> 6, w = tid & 63; s->rkeys[r][w] = tanhf(xi[tid]); }
        if (tid < 64) {
            s->wkey[tid]  = tanhf(xi[260 + tid]);
            s->erase[tid] = sigm (xi[325 + tid]);
            s->wvec[tid]  = tanhf(xi[389 + tid]);
        } else if (tid < 68) s->rstr[tid - 64] = splus(xi[256 + tid - 64]);
        else if (tid < 72)   s->fg[tid - 68]   = sigm (xi[453 + tid - 68]);
        else if (tid == 72)  s->scal[S_WSTR]   = splus(xi[324]);
        else if (tid == 73)  s->scal[S_AG]     = sigm (xi[457]);
        else if (tid == 74)  s->scal[S_WG]     = sigm (xi[458]);
        else if (tid >= 80 && tid < 84) {
            int r = tid - 80;
            float x0 = xi[459 + 3*r], x1 = xi[460 + 3*r], x2 = xi[461 + 3*r];
            float m = fmaxf(x0, fmaxf(x1, x2));
            float e0 = expf(x0 - m), e1 = expf(x1 - m), e2 = expf(x2 - m);
            float inv = 1.f / (e0 + e1 + e2);
            s->modes[r][0] = e0*inv; s->modes[r][1] = e1*inv; s->modes[r][2] = e2*inv;
        }
        __syncthreads();

        if (tid < 128) {
            float us = s->usage[tid] + (1.f - s->usage[tid]) * s->ww[tid];
            float ret = 1.f;
#pragma unroll
            for (int r = 0; r < RRq; r++) ret *= (1.f - s->fg[r] * s->rw[r][tid]);
            s->usage[tid] = us * ret;
            float ss = 0.f;
#pragma unroll 8
            for (int w = 0; w < WWq; w++) { float v = s->mem[tid][w]; ss += v * v; }
            s->norms[tid] = sqrtf(ss);
        } else if (tid < 160) {
            int l = tid - 128;
            float pq = s->wkey[l]*s->wkey[l] + s->wkey[l+32]*s->wkey[l+32];
            pq = warp_sum(pq);
            if (l == 0) s->scal[S_KN] = sqrtf(pq);
        } else if (tid < 164) {
            int r = tid - 160; float ss = 0.f;
            for (int w = 0; w < WWq; w++) ss += s->rkeys[r][w]*s->rkeys[r][w];
            s->rknorm[r] = sqrtf(ss);
        }
        __syncthreads();

        if (tid < 128) {
            float d = 0.f;
#pragma unroll 8
            for (int w = 0; w < WWq; w++) d += s->wkey[w] * s->mem[tid][w];
            s->wc[tid] = d / ((s->norms[tid] + EPSq) * (s->scal[S_KN] + EPSq)) * s->scal[S_WSTR];
        }
        __syncthreads();
        if (tid < 32) {
            float v0 = s->wc[tid], v1 = s->wc[tid+32], v2 = s->wc[tid+64], v3 = s->wc[tid+96];
            float mx = warp_max(fmaxf(fmaxf(v0, v1), fmaxf(v2, v3)));
            v0 = expf(v0-mx); v1 = expf(v1-mx); v2 = expf(v2-mx); v3 = expf(v3-mx);
            float inv = 1.f / warp_sum(v0 + v1 + v2 + v3);
            s->wc[tid] = v0*inv; s->wc[tid+32] = v1*inv; s->wc[tid+64] = v2*inv; s->wc[tid+96] = v3*inv;
        }
        __syncthreads();

        if (tid < 128) s->u[tid] = DELTAq + (1.f - DELTAq) * s->usage[tid];
        __syncthreads();
        if (tid < 128) {
            float ui = s->u[tid]; int rk = 0;
            for (int j = 0; j < 128; j++) {
                float uj = s->u[j];
                rk += (uj < ui) || (uj == ui && j < tid);
            }
            s->rank[tid] = rk;
            s->su[rk] = ui;
        }
        __syncthreads();
        if (tid < 128) s->pe[tid] = s->su[tid];
        __syncthreads();
        for (int d = 1; d < 128; d <<= 1) {
            float v = 1.f;
            if (tid < 128 && tid >= d) v = s->pe[tid - d];
            __syncthreads();
            if (tid < 128 && tid >= d) s->pe[tid] *= v;
            __syncthreads();
        }
        if (tid < 128) {
            int rk = s->rank[tid];
            float excl = rk ? s->pe[rk - 1] : 1.f;
            float alloc = (1.f - s->u[tid]) * excl;
            float ag = s->scal[S_AG], wg = s->scal[S_WG];
            s->ww[tid] = wg * (ag * alloc + (1.f - ag) * s->wc[tid]);
        }
        __syncthreads();
        if (tid < 32) {
            float v = s->ww[tid] + s->ww[tid+32] + s->ww[tid+64] + s->ww[tid+96];
            v = warp_sum(v);
            if (tid == 0) s->scal[S_SWW] = v;
        }
        __syncthreads();

        {
            int w = tid & 63, ng = tid >> 6;
            for (int i = 0; i < 32; i++) {
                int n = ng * 32 + i;
                float wwn = s->ww[n];
                s->mem[n][w] = s->mem[n][w] * (1.f - wwn * s->erase[w]) + wwn * s->wvec[w];
            }
        }
        {
            int i = tid >> 1, j0 = (tid & 1) * 64;
            float wwi = s->ww[i];
            for (int jj = 0; jj < 64; jj++) {
                int j = j0 + jj;
                float l = (1.f - wwi - s->ww[j]) * s->link[i][j] + wwi * s->prec[j];
                s->link[i][j] = (i == j) ? 0.f : l;
            }
        }
        __syncthreads();
        if (tid < 128) {
            s->prec[tid] = (1.f - s->scal[S_SWW]) * s->prec[tid] + s->ww[tid];
            float ss = 0.f;
#pragma unroll 8
            for (int w = 0; w < WWq; w++) { float v = s->mem[tid][w]; ss += v * v; }
            s->norms[tid] = sqrtf(ss);
        }
        __syncthreads();

        for (int q = tid; q < 512; q += 256) {
            int r = q >> 7, n = q & 127;
            float d = 0.f;
#pragma unroll 8
            for (int w = 0; w < WWq; w++) d += s->rkeys[r][w] * s->mem[n][w];
            s->rc[r][n] = d / ((s->norms[n] + EPSq) * (s->rknorm[r] + EPSq)) * s->rstr[r];
        }
        __syncthreads();
        if (tid < 128) {
            int r = tid >> 5, l = tid & 31;
            float v0 = s->rc[r][l], v1 = s->rc[r][l+32], v2 = s->rc[r][l+64], v3 = s->rc[r][l+96];
            float mx = warp_max(fmaxf(fmaxf(v0, v1), fmaxf(v2, v3)));
            v0 = expf(v0-mx); v1 = expf(v1-mx); v2 = expf(v2-mx); v3 = expf(v3-mx);
            float inv = 1.f / warp_sum(v0 + v1 + v2 + v3);
            s->rc[r][l] = v0*inv; s->rc[r][l+32] = v1*inv; s->rc[r][l+64] = v2*inv; s->rc[r][l+96] = v3*inv;
        }
        __syncthreads();

        for (int q = tid; q < 512; q += 256) {
            int r = q >> 7, n = q & 127;
            float f = 0.f, bw = 0.f;
#pragma unroll 4
            for (int m = 0; m < 128; m++) {
                float rv = s->rw[r][m];
                f  += rv * s->link[n][m];
                bw += rv * s->link[m][n];
            }
            s->fwd[r][n] = f; s->bwd[r][n] = bw;
        }
        __syncthreads();
        for (int q = tid; q < 512; q += 256) {
            int r = q >> 7, n = q & 127;
            s->rw2[r][n] = s->modes[r][0]*s->bwd[r][n] + s->modes[r][1]*s->rc[r][n] + s->modes[r][2]*s->fwd[r][n];
        }
        __syncthreads();
        for (int q = tid; q < 512; q += 256) { int r = q >> 7, n = q & 127; s->rw[r][n] = s->rw2[r][n]; }
        __syncthreads();

        {
            int r = tid >> 6, w = tid & 63;
            float acc = 0.f;
#pragma unroll 4
            for (int n = 0; n < 128; n++) acc += s->rw[r][n] * s->mem[n][w];
            cat[((size_t)t * BB + b) * CATW + 512 + tid] = acc;
        }
        __syncthreads();
    }
}

__global__ void gather_hid(float* __restrict__ out, const int* __restrict__ lens) {
    int b = blockIdx.x, i = threadIdx.x;
    int t = lens[b] - 1;
    out[(size_t)TT * BB * IDIMq + (size_t)b * IDIMq + i] = out[((size_t)t * BB + b) * IDIMq + i];
}

extern "C" void kernel_launch(void* const* d_in, const int* in_sizes, int n_in,
                              void* d_out, int out_size) {
    const float* embs = (const float*)d_in[0];
    const int*   lens = (const int*)  d_in[1];
    const float* Wih0 = (const float*)d_in[2];
    const float* Whh0 = (const float*)d_in[3];
    const float* bih0 = (const float*)d_in[4];
    const float* bhh0 = (const float*)d_in[5];
    const float* Wih1 = (const float*)d_in[6];
    const float* Whh1 = (const float*)d_in[7];
    const float* bih1 = (const float*)d_in[8];
    const float* bhh1 = (const float*)d_in[9];
    const float* Wxi  = (const float*)d_in[10];
    const float* bxi  = (const float*)d_in[11];
    const float* Wout = (const float*)d_in[12];
    const float* bout = (const float*)d_in[13];
    float* out = (float*)d_out;

    float *G, *h0, *h1, *cat, *xi;
    cudaGetSymbolAddress((void**)&G,   g_G);
    cudaGetSymbolAddress((void**)&h0,  g_h0);
    cudaGetSymbolAddress((void**)&h1,  g_h1);
    cudaGetSymbolAddress((void**)&cat, g_cat);
    cudaGetSymbolAddress((void**)&xi,  g_xi);

    cudaFuncSetAttribute(memory_kernel, cudaFuncAttributeMaxDynamicSharedMemorySize,
                         (int)sizeof(MemSmem));
    cudaFuncSetAttribute(lstm_persist, cudaFuncAttributeMaxDynamicSharedMemorySize,
                         SM_FLOATS * 4);

    // Gpre0^T = (embs @ Wih0[:, :256]^T + bih0 + bhh0) transposed  [t][2048][64]
    sgemm_bt_tg<<<dim3(16, 64), 256>>>(embs, IDIMq, Wih0, CDIMq, G, bih0, bhh0, 2048, IDIMq);

    // layer 0: all 128 steps, one persistent kernel
    lstm_persist<<<NBLK, 256, SM_FLOATS * 4>>>(G, Whh0, h0, nullptr);

    // Gpre1^T = (h0 @ Wih1^T + bih1 + bhh1) transposed
    sgemm_bt_tg<<<dim3(16, 64), 256>>>(h0, CDIMq, Wih1, CDIMq, G, bih1, bhh1, 2048, CDIMq);

    // layer 1: all 128 steps (also writes clip(h1) into cat)
    lstm_persist<<<NBLK, 256, SM_FLOATS * 4>>>(G, Whh1, h1, cat);

    // xi = clip(h1) @ Wxi^T + bxi
    sgemm_bt<<<dim3(4, 64), 256>>>(cat, CATW, Wxi, CDIMq, xi, IFACEq, bxi, nullptr, IFACEq, CDIMq);

    memory_kernel<<<64, 256, sizeof(MemSmem)>>>(xi, cat);

    // y = cat @ Wout^T + bout
    sgemm_bt<<<dim3(2, 64), 256>>>(cat, CATW, Wout, CATW, out, IDIMq, bout, nullptr, IDIMq, CATW);

    gather_hid<<<64, 256>>>(out, lens);
}